// round 16
// baseline (speedup 1.0000x reference)
#include <cuda_runtime.h>
#include <cuda_fp16.h>
#include <cstdint>
#include <cstddef>
#include <cstring>

#define NTIME 20
#define V     128
#define F     128
#define LRELU_ALPHA 0.2f
#define LOG2E 1.4426950408889634f
#define ALOG2E (LRELU_ALPHA * LOG2E)

#define OUT_HP_ELEMS   (NTIME * V * F)
#define ATT_OFF        OUT_HP_ELEMS

__device__ __half g_Whh[NTIME * V * F];       // Wh in half (only used for h_prime)
__device__ float  g_P1[NTIME * V * F];        // exp2(log2e * e1)
__device__ float  g_N1[NTIME * V * F];        // exp2(0.2 * log2e * e1)
__device__ __half g_PN2[NTIME * V * F * 2];   // interleaved half (P2, N2) per f

__device__ __forceinline__ float ex2(float x) {
    float r; asm("ex2.approx.f32 %0, %1;" : "=f"(r) : "f"(x)); return r;
}

// ----------------------------------------------------------------------------
// Kernel 1 (fused, f-quad vectorized): per block of MT=16 rows:
//   phase 1: Wh = h @ W        -> smem whs (fp32) + g_Whh (half)
//   phase 2: e1 = Whs @ a1, e2 = Whs @ a2  -> ex2 tables
// 512 threads: fq = tid&31 (f-quad, f = fq*4), rg = tid>>5 (row 0..15).
// B-matrix loads are LDG.128 over 4 consecutive f (1 load per k instead of 4
// scalar loads); h/Wh broadcast from smem (warp-uniform row). grid = 160.
// ----------------------------------------------------------------------------
#define MT 16

__global__ void __launch_bounds__(512) gemm_fused(
    const float* __restrict__ h,
    const float* __restrict__ W,
    const float* __restrict__ a)
{
    __shared__ float hs[MT * F];
    __shared__ float whs[MT * F];

    const int tid = threadIdx.x;
    const int fq  = tid & 31;        // f-quad: columns fq*4 .. fq*4+3
    const int rg  = tid >> 5;        // row 0..15
    const int m0  = blockIdx.x * MT;

    // stage h tile: 2048 floats = 512 float4, 1 per thread
    ((float4*)hs)[tid] = ((const float4*)(h + (size_t)m0 * F))[tid];
    __syncthreads();

    // ---- phase 1: Wh row rg, columns fq*4..+3 ----
    {
        float4 acc = {0.f, 0.f, 0.f, 0.f};
        const float* hrow = hs + rg * F;
#pragma unroll 4
        for (int k = 0; k < F; k++) {
            const float4 wv = *(const float4*)(W + (size_t)k * F + fq * 4);
            const float  hv = hrow[k];                 // warp-uniform broadcast
            acc.x = fmaf(hv, wv.x, acc.x);
            acc.y = fmaf(hv, wv.y, acc.y);
            acc.z = fmaf(hv, wv.z, acc.z);
            acc.w = fmaf(hv, wv.w, acc.w);
        }
        *(float4*)(whs + rg * F + fq * 4) = acc;
        // Wh in half: 4 halves = 8 bytes
        __half2 p0 = __floats2half2_rn(acc.x, acc.y);
        __half2 p1 = __floats2half2_rn(acc.z, acc.w);
        uint2 pk; memcpy(&pk.x, &p0, 4); memcpy(&pk.y, &p1, 4);
        *(uint2*)(g_Whh + (size_t)(m0 + rg) * F + fq * 4) = pk;
    }
    __syncthreads();

    // ---- phase 2: e1, e2 row rg ----
    {
        float4 ac1 = {0.f, 0.f, 0.f, 0.f};
        float4 ac2 = {0.f, 0.f, 0.f, 0.f};
        const float* wrow = whs + rg * F;
#pragma unroll 4
        for (int k = 0; k < F; k++) {
            const float4 a1v = *(const float4*)(a + (size_t)k * F + fq * 4);
            const float4 a2v = *(const float4*)(a + (size_t)(F + k) * F + fq * 4);
            const float  wv  = wrow[k];                // warp-uniform broadcast
            ac1.x = fmaf(wv, a1v.x, ac1.x);
            ac1.y = fmaf(wv, a1v.y, ac1.y);
            ac1.z = fmaf(wv, a1v.z, ac1.z);
            ac1.w = fmaf(wv, a1v.w, ac1.w);
            ac2.x = fmaf(wv, a2v.x, ac2.x);
            ac2.y = fmaf(wv, a2v.y, ac2.y);
            ac2.z = fmaf(wv, a2v.z, ac2.z);
            ac2.w = fmaf(wv, a2v.w, ac2.w);
        }

        const size_t idx = (size_t)(m0 + rg) * F + fq * 4;
        float4 P1v, N1v;
        P1v.x = ex2(LOG2E * ac1.x);  N1v.x = ex2(ALOG2E * ac1.x);
        P1v.y = ex2(LOG2E * ac1.y);  N1v.y = ex2(ALOG2E * ac1.y);
        P1v.z = ex2(LOG2E * ac1.z);  N1v.z = ex2(ALOG2E * ac1.z);
        P1v.w = ex2(LOG2E * ac1.w);  N1v.w = ex2(ALOG2E * ac1.w);
        *(float4*)(g_P1 + idx) = P1v;
        *(float4*)(g_N1 + idx) = N1v;

        // PN2 interleaved halves: (P2,N2) per f -> 8 halves = 16B = uint4
        __half2 q0 = __floats2half2_rn(ex2(LOG2E * ac2.x), ex2(ALOG2E * ac2.x));
        __half2 q1 = __floats2half2_rn(ex2(LOG2E * ac2.y), ex2(ALOG2E * ac2.y));
        __half2 q2 = __floats2half2_rn(ex2(LOG2E * ac2.z), ex2(ALOG2E * ac2.z));
        __half2 q3 = __floats2half2_rn(ex2(LOG2E * ac2.w), ex2(ALOG2E * ac2.w));
        uint4 pk;
        memcpy(&pk.x, &q0, 4); memcpy(&pk.y, &q1, 4);
        memcpy(&pk.z, &q2, 4); memcpy(&pk.w, &q3, 4);
        *(uint4*)(g_PN2 + idx * 2) = pk;
    }
}

// ----------------------------------------------------------------------------
// Kernel 2: attention (R15 structure, unchanged — best measured):
//  - PN2 tile half in smem (LDS.64/j), Wh half tile in smem (LDS.32/j)
//  - p = max(P1*P2, N1*N2)
// j-split: two warps per (i, f-half), each owning 64 j's; partials via smem.
// Block = 512 threads, grid = 32 x 20 = 640 (10240 warps), smem 56KB, 3 CTA/SM.
// ----------------------------------------------------------------------------
#define FH  64
#define IPB 8
#define ATTN_SMEM_BYTES (2 * V * FH * 2 + V * FH * 2 + 16 * 32 * 16)

__global__ void __launch_bounds__(512, 3) attn_fused(
    const float* __restrict__ adj,
    float* __restrict__ out)
{
    extern __shared__ char smc[];
    __half* pn2 = (__half*)smc;                            // [V][FH][2]
    __half* whs = (__half*)(smc + 2 * V * FH * 2);         // [V][FH]
    float4* red = (float4*)(smc + 3 * V * FH * 2);         // [16][32]

    const int t    = blockIdx.y;
    const int bx   = blockIdx.x;      // 0..31
    const int fh   = bx & 1;
    const int ig   = bx >> 1;         // 0..15
    const int tid  = threadIdx.x;
    const int lane = tid & 31;
    const int w    = tid >> 5;        // warp 0..15
    const int il   = w >> 1;          // local i 0..7
    const int jh   = w & 1;           // j-half
    const int i    = ig * IPB + il;
    const int f2   = fh * FH + lane * 2;

    uint32_t bits[2];
    {
        const float* arow = adj + (size_t)i * V + jh * 64;
        bits[0] = __ballot_sync(0xFFFFFFFFu, arow[lane]      > 0.0f);
        bits[1] = __ballot_sync(0xFFFFFFFFu, arow[32 + lane] > 0.0f);
    }

    // coop load PN2 tile (2048 float4, 4/thread) + Wh half tile (1024 float4, 2/thread)
    {
        const __half* src = g_PN2 + ((size_t)t * V * F + fh * FH) * 2;
#pragma unroll
        for (int u = 0; u < 4; u++) {
            const int idx = tid + u * 512;
            const int j = idx >> 4, c = idx & 15;
            ((float4*)pn2)[idx] = *(const float4*)(src + (size_t)j * F * 2 + c * 8);
        }
        const __half* wsrc = g_Whh + (size_t)t * V * F + fh * FH;
#pragma unroll
        for (int u = 0; u < 2; u++) {
            const int idx = tid + u * 512;
            const int j = idx >> 3, c = idx & 7;
            ((float4*)whs)[idx] = *(const float4*)(wsrc + (size_t)j * F + c * 8);
        }
    }

    const float2 p1 = *(const float2*)(g_P1 + ((size_t)t * V + i) * F + f2);
    const float2 n1 = *(const float2*)(g_N1 + ((size_t)t * V + i) * F + f2);
    __syncthreads();

    const __half* pnl = pn2 + (jh * 64) * FH * 2 + lane * 4;
    const __half* whl = whs + (jh * 64) * FH + lane * 2;

    // Pass A: partial sums over own 64 j's (all shared-memory)
    float s0 = 0.0f, s1 = 0.0f, a0 = 0.0f, a1 = 0.0f;
#pragma unroll
    for (int ww = 0; ww < 2; ww++) {
        const uint32_t bw = bits[ww];
        const __half* pnw = pnl + ww * 32 * FH * 2;
        const __half* whw = whl + ww * 32 * FH;
#pragma unroll
        for (int b = 0; b < 32; b++) {
            if (bw & (1u << b)) {
                const uint2 qu = *(const uint2*)(pnw + b * FH * 2);
                const float2 q0 = __half22float2(*(const __half2*)&qu.x);
                const float2 q1 = __half22float2(*(const __half2*)&qu.y);
                const float2 wv = __half22float2(*(const __half2*)(whw + b * FH));
                const float v0 = fmaxf(p1.x * q0.x, n1.x * q0.y);
                const float v1 = fmaxf(p1.y * q1.x, n1.y * q1.y);
                s0 += v0;  s1 += v1;
                a0 = fmaf(v0, wv.x, a0);
                a1 = fmaf(v1, wv.y, a1);
            }
        }
    }

    red[w * 32 + lane] = make_float4(s0, s1, a0, a1);
    __syncthreads();
    {
        const float4 o = red[(w ^ 1) * 32 + lane];
        s0 += o.x; s1 += o.y; a0 += o.z; a1 += o.w;
    }

    const float r0 = 1.0f / s0;
    const float r1 = 1.0f / s1;

    if (jh == 0) {
        const float hp0 = a0 * r0;
        const float hp1 = a1 * r1;
        float2 o;
        o.x = (hp0 > 0.0f) ? hp0 : expm1f(hp0);
        o.y = (hp1 > 0.0f) ? hp1 : expm1f(hp1);
        *(float2*)(out + ((size_t)t * V + i) * F + f2) = o;
    }

    // Pass B: prescaled products, stream normalized attention
    const float P1ra = p1.x * r0, N1ra = n1.x * r0;
    const float P1rb = p1.y * r1, N1rb = n1.y * r1;

    float* ab = out + ATT_OFF + (((size_t)t * V + i) * V + jh * 64) * F + f2;
#pragma unroll
    for (int ww = 0; ww < 2; ww++) {
        const uint32_t bw = bits[ww];
        const __half* pnw = pnl + ww * 32 * FH * 2;
        float* abw = ab + (size_t)ww * 32 * F;
#pragma unroll
        for (int b = 0; b < 32; b++) {
            float2 pv;
            if (bw & (1u << b)) {
                const uint2 qu = *(const uint2*)(pnw + b * FH * 2);
                const float2 q0 = __half22float2(*(const __half2*)&qu.x);
                const float2 q1 = __half22float2(*(const __half2*)&qu.y);
                pv.x = fmaxf(P1ra * q0.x, N1ra * q0.y);
                pv.y = fmaxf(P1rb * q1.x, N1rb * q1.y);
            } else {
                pv.x = 0.0f; pv.y = 0.0f;
            }
            __stcs((float2*)(abw + b * F), pv);
        }
    }
}

// ----------------------------------------------------------------------------
extern "C" void kernel_launch(void* const* d_in, const int* in_sizes, int n_in,
                              void* d_out, int out_size)
{
    const float* h   = (const float*)d_in[0];   // [2560,128]
    const float* adj = (const float*)d_in[1];   // [128,128,1]
    const float* W   = (const float*)d_in[2];   // [128,128]
    const float* a   = (const float*)d_in[3];   // [256,128]
    float* out = (float*)d_out;

    cudaFuncSetAttribute(attn_fused, cudaFuncAttributeMaxDynamicSharedMemorySize,
                         ATTN_SMEM_BYTES);

    gemm_fused<<<160, 512>>>(h, W, a);

    dim3 g2(32, NTIME);
    attn_fused<<<g2, 512, ATTN_SMEM_BYTES>>>(adj, out);
}

// round 17
// speedup vs baseline: 1.1149x; 1.1149x over previous
#include <cuda_runtime.h>
#include <cuda_fp16.h>
#include <cstdint>
#include <cstddef>
#include <cstring>

#define NTIME 20
#define V     128
#define F     128
#define LRELU_ALPHA 0.2f
#define LOG2E 1.4426950408889634f
#define ALOG2E (LRELU_ALPHA * LOG2E)

#define OUT_HP_ELEMS   (NTIME * V * F)
#define ATT_OFF        OUT_HP_ELEMS

__device__ __half g_Whh[NTIME * V * F];       // Wh in half (only used for h_prime)
__device__ float  g_P1[NTIME * V * F];        // exp2(log2e * e1)
__device__ float  g_N1[NTIME * V * F];        // exp2(0.2 * log2e * e1)
__device__ __half g_PN2[NTIME * V * F * 2];   // interleaved half (P2, N2) per f

__device__ __forceinline__ float ex2(float x) {
    float r; asm("ex2.approx.f32 %0, %1;" : "=f"(r) : "f"(x)); return r;
}

// ----------------------------------------------------------------------------
// Kernel 1 (fused, exact R15 shape — best measured): per block of MT=4 rows:
//   phase 1: Wh = h @ W        -> smem whs (fp32) + g_Whh (half)
//   phase 2: e1 = Whs @ a1, e2 = Whs @ a2  -> ex2 tables
// 256 threads: f = tid&127, hf = tid>>7, 2 rows/thread. grid = 640.
// ----------------------------------------------------------------------------
#define MT 4

__global__ void __launch_bounds__(256) gemm_fused(
    const float* __restrict__ h,
    const float* __restrict__ W,
    const float* __restrict__ a)
{
    __shared__ float hs[MT * F];
    __shared__ float whs[MT * F];

    const int tid = threadIdx.x;
    const int f   = tid & 127;
    const int hf  = tid >> 7;
    const int m0  = blockIdx.x * MT;

    if (tid < 128)
        ((float4*)hs)[tid] = ((const float4*)(h + (size_t)m0 * F))[tid];
    __syncthreads();

    // ---- phase 1: Wh ----
    {
        float acc[2] = {0.f, 0.f};
#pragma unroll 8
        for (int k4 = 0; k4 < F / 4; k4++) {
            float mv[4];
#pragma unroll
            for (int u = 0; u < 4; u++)
                mv[u] = __ldg(W + (k4 * 4 + u) * F + f);
#pragma unroll
            for (int r = 0; r < 2; r++) {
                const float4 hv = ((const float4*)(hs + (hf * 2 + r) * F))[k4];
                acc[r] = fmaf(hv.x, mv[0], acc[r]);
                acc[r] = fmaf(hv.y, mv[1], acc[r]);
                acc[r] = fmaf(hv.z, mv[2], acc[r]);
                acc[r] = fmaf(hv.w, mv[3], acc[r]);
            }
        }
#pragma unroll
        for (int r = 0; r < 2; r++) {
            const int row = hf * 2 + r;
            whs[row * F + f] = acc[r];
            g_Whh[(size_t)(m0 + row) * F + f] = __float2half_rn(acc[r]);
        }
    }
    __syncthreads();

    // ---- phase 2: e1, e2 from whs ----
    {
        float ac1[2] = {0.f, 0.f};
        float ac2[2] = {0.f, 0.f};
#pragma unroll 8
        for (int k4 = 0; k4 < F / 4; k4++) {
            float a1v[4], a2v[4];
#pragma unroll
            for (int u = 0; u < 4; u++) {
                a1v[u] = __ldg(a + (k4 * 4 + u) * F + f);
                a2v[u] = __ldg(a + (F + k4 * 4 + u) * F + f);
            }
#pragma unroll
            for (int r = 0; r < 2; r++) {
                const float4 wv = ((const float4*)(whs + (hf * 2 + r) * F))[k4];
                ac1[r] = fmaf(wv.x, a1v[0], ac1[r]);
                ac1[r] = fmaf(wv.y, a1v[1], ac1[r]);
                ac1[r] = fmaf(wv.z, a1v[2], ac1[r]);
                ac1[r] = fmaf(wv.w, a1v[3], ac1[r]);
                ac2[r] = fmaf(wv.x, a2v[0], ac2[r]);
                ac2[r] = fmaf(wv.y, a2v[1], ac2[r]);
                ac2[r] = fmaf(wv.z, a2v[2], ac2[r]);
                ac2[r] = fmaf(wv.w, a2v[3], ac2[r]);
            }
        }
#pragma unroll
        for (int r = 0; r < 2; r++) {
            const size_t idx = (size_t)(m0 + hf * 2 + r) * F + f;
            g_P1[idx] = ex2(LOG2E  * ac1[r]);
            g_N1[idx] = ex2(ALOG2E * ac1[r]);
            const float P2 = ex2(LOG2E  * ac2[r]);
            const float N2 = ex2(ALOG2E * ac2[r]);
            *(__half2*)(g_PN2 + idx * 2) = __floats2half2_rn(P2, N2);
        }
    }
}

// ----------------------------------------------------------------------------
// Kernel 2: attention (R15 loop body, 1024-thread blocks for 100% occupancy):
//  - 32 warps = 16 i x 2 jh; tile shared by 16 i (staging traffic halves)
//  - 2 CTAs/SM x 32 warps = 64 warps/SM (theoretical 100%)
//  - __launch_bounds__(1024,2) -> 32 regs/thread cap (live set ~30, should fit)
// smem = PN2 32KB + Wh 16KB + red 16KB = 64KB.
// ----------------------------------------------------------------------------
#define FH  64
#define IPB 16
#define ATTN_SMEM_BYTES (2 * V * FH * 2 + V * FH * 2 + 32 * 32 * 16)

__global__ void __launch_bounds__(1024, 2) attn_fused(
    const float* __restrict__ adj,
    float* __restrict__ out)
{
    extern __shared__ char smc[];
    __half* pn2 = (__half*)smc;                            // [V][FH][2]
    __half* whs = (__half*)(smc + 2 * V * FH * 2);         // [V][FH]
    float4* red = (float4*)(smc + 3 * V * FH * 2);         // [32][32]

    const int t    = blockIdx.y;
    const int bx   = blockIdx.x;      // 0..15
    const int fh   = bx & 1;
    const int ig   = bx >> 1;         // 0..7
    const int tid  = threadIdx.x;
    const int lane = tid & 31;
    const int w    = tid >> 5;        // warp 0..31
    const int il   = w >> 1;          // local i 0..15
    const int jh   = w & 1;           // j-half
    const int i    = ig * IPB + il;
    const int f2   = fh * FH + lane * 2;

    uint32_t bits[2];
    {
        const float* arow = adj + (size_t)i * V + jh * 64;
        bits[0] = __ballot_sync(0xFFFFFFFFu, arow[lane]      > 0.0f);
        bits[1] = __ballot_sync(0xFFFFFFFFu, arow[32 + lane] > 0.0f);
    }

    // coop load PN2 tile (2048 float4, 2/thread) + Wh half tile (1024 float4, 1/thread)
    {
        const __half* src = g_PN2 + ((size_t)t * V * F + fh * FH) * 2;
#pragma unroll
        for (int u = 0; u < 2; u++) {
            const int idx = tid + u * 1024;         // 0..2047
            const int j = idx >> 4, c = idx & 15;
            ((float4*)pn2)[idx] = *(const float4*)(src + (size_t)j * F * 2 + c * 8);
        }
        const __half* wsrc = g_Whh + (size_t)t * V * F + fh * FH;
        {
            const int j = tid >> 3, c = tid & 7;
            ((float4*)whs)[tid] = *(const float4*)(wsrc + (size_t)j * F + c * 8);
        }
    }

    const float2 p1 = *(const float2*)(g_P1 + ((size_t)t * V + i) * F + f2);
    const float2 n1 = *(const float2*)(g_N1 + ((size_t)t * V + i) * F + f2);
    __syncthreads();

    const __half* pnl = pn2 + (jh * 64) * FH * 2 + lane * 4;
    const __half* whl = whs + (jh * 64) * FH + lane * 2;

    // Pass A: partial sums over own 64 j's (all shared-memory)
    float s0 = 0.0f, s1 = 0.0f, a0 = 0.0f, a1 = 0.0f;
#pragma unroll
    for (int ww = 0; ww < 2; ww++) {
        const uint32_t bw = bits[ww];
        const __half* pnw = pnl + ww * 32 * FH * 2;
        const __half* whw = whl + ww * 32 * FH;
#pragma unroll
        for (int b = 0; b < 32; b++) {
            if (bw & (1u << b)) {
                const uint2 qu = *(const uint2*)(pnw + b * FH * 2);
                const float2 q0 = __half22float2(*(const __half2*)&qu.x);
                const float2 q1 = __half22float2(*(const __half2*)&qu.y);
                const float2 wv = __half22float2(*(const __half2*)(whw + b * FH));
                const float v0 = fmaxf(p1.x * q0.x, n1.x * q0.y);
                const float v1 = fmaxf(p1.y * q1.x, n1.y * q1.y);
                s0 += v0;  s1 += v1;
                a0 = fmaf(v0, wv.x, a0);
                a1 = fmaf(v1, wv.y, a1);
            }
        }
    }

    red[w * 32 + lane] = make_float4(s0, s1, a0, a1);
    __syncthreads();
    {
        const float4 o = red[(w ^ 1) * 32 + lane];
        s0 += o.x; s1 += o.y; a0 += o.z; a1 += o.w;
    }

    const float r0 = 1.0f / s0;
    const float r1 = 1.0f / s1;

    if (jh == 0) {
        const float hp0 = a0 * r0;
        const float hp1 = a1 * r1;
        float2 o;
        o.x = (hp0 > 0.0f) ? hp0 : expm1f(hp0);
        o.y = (hp1 > 0.0f) ? hp1 : expm1f(hp1);
        *(float2*)(out + ((size_t)t * V + i) * F + f2) = o;
    }

    // Pass B: prescaled products, stream normalized attention
    const float P1ra = p1.x * r0, N1ra = n1.x * r0;
    const float P1rb = p1.y * r1, N1rb = n1.y * r1;

    float* ab = out + ATT_OFF + (((size_t)t * V + i) * V + jh * 64) * F + f2;
#pragma unroll
    for (int ww = 0; ww < 2; ww++) {
        const uint32_t bw = bits[ww];
        const __half* pnw = pnl + ww * 32 * FH * 2;
        float* abw = ab + (size_t)ww * 32 * F;
#pragma unroll
        for (int b = 0; b < 32; b++) {
            float2 pv;
            if (bw & (1u << b)) {
                const uint2 qu = *(const uint2*)(pnw + b * FH * 2);
                const float2 q0 = __half22float2(*(const __half2*)&qu.x);
                const float2 q1 = __half22float2(*(const __half2*)&qu.y);
                pv.x = fmaxf(P1ra * q0.x, N1ra * q0.y);
                pv.y = fmaxf(P1rb * q1.x, N1rb * q1.y);
            } else {
                pv.x = 0.0f; pv.y = 0.0f;
            }
            __stcs((float2*)(abw + b * F), pv);
        }
    }
}

// ----------------------------------------------------------------------------
extern "C" void kernel_launch(void* const* d_in, const int* in_sizes, int n_in,
                              void* d_out, int out_size)
{
    const float* h   = (const float*)d_in[0];   // [2560,128]
    const float* adj = (const float*)d_in[1];   // [128,128,1]
    const float* W   = (const float*)d_in[2];   // [128,128]
    const float* a   = (const float*)d_in[3];   // [256,128]
    float* out = (float*)d_out;

    cudaFuncSetAttribute(attn_fused, cudaFuncAttributeMaxDynamicSharedMemorySize,
                         ATTN_SMEM_BYTES);

    gemm_fused<<<640, 256>>>(h, W, a);

    dim3 g2(16, NTIME);
    attn_fused<<<g2, 1024, ATTN_SMEM_BYTES>>>(adj, out);
}